// round 8
// baseline (speedup 1.0000x reference)
#include <cuda_runtime.h>

#define NK 7

// Coefficients of the rational function P(T)/Q(T), each duplicated as
// float2 {c,c} so the main kernel can LDG.64 straight into packed-f32x2 form.
__device__ float2 g_pq[16];   // [0..7] = P coeffs, [8..15] = Q coeffs

// ---------------------------------------------------------------------------
// One-thread pre-kernel: build P,Q coefficients in fp64.
//   Q(T) = prod_k (1 + c_k T)
//   P(T) = sum_k a_k (T + c_k) prod_{j!=k} (1 + c_j T)
// so that  sum_k a_k tanh(5x + 5 b_k) == P(tanh 5x) / Q(tanh 5x)  exactly.
// ---------------------------------------------------------------------------
__global__ void precompute_kernel(const float* __restrict__ w)
{
    if (threadIdx.x != 0 || blockIdx.x != 0) return;

    double a[NK], c[NK];
    for (int k = 0; k < NK; k++) {
        a[k] = (double)w[2 * k];
        c[k] = tanh(5.0 * (double)w[2 * k + 1]);
    }

    double q[8] = {1, 0, 0, 0, 0, 0, 0, 0};
    for (int k = 0; k < NK; k++)
        for (int i = 7; i >= 1; i--)
            q[i] += c[k] * q[i - 1];

    double p[8] = {0, 0, 0, 0, 0, 0, 0, 0};
    for (int k = 0; k < NK; k++) {
        double r[8] = {1, 0, 0, 0, 0, 0, 0, 0};
        for (int j = 0; j < NK; j++) {
            if (j == k) continue;
            for (int i = 7; i >= 1; i--)
                r[i] += c[j] * r[i - 1];
        }
        // multiply r (deg 6) by (T + c_k)
        double s[8];
        s[0] = c[k] * r[0];
        for (int i = 1; i <= 7; i++) s[i] = r[i - 1] + c[k] * r[i];
        for (int i = 0; i <= 7; i++) p[i] += a[k] * s[i];
    }

    for (int i = 0; i < 8; i++) {
        float fp = (float)p[i];
        float fq = (float)q[i];
        g_pq[i]     = make_float2(fp, fp);
        g_pq[8 + i] = make_float2(fq, fq);
    }
}

// ---------------------------------------------------------------------------
// Packed f32x2 helpers (Blackwell FFMA2 path)
// ---------------------------------------------------------------------------
__device__ __forceinline__ float tanh_approx(float x) {
    float y; asm("tanh.approx.f32 %0, %1;" : "=f"(y) : "f"(x)); return y;
}
__device__ __forceinline__ float rcp_approx(float x) {
    float y; asm("rcp.approx.f32 %0, %1;" : "=f"(y) : "f"(x)); return y;
}
__device__ __forceinline__ unsigned long long fma2(
    unsigned long long a, unsigned long long b, unsigned long long c) {
    unsigned long long d;
    asm("fma.rn.f32x2 %0, %1, %2, %3;" : "=l"(d) : "l"(a), "l"(b), "l"(c));
    return d;
}
__device__ __forceinline__ unsigned long long pack2(float lo, float hi) {
    unsigned long long d;
    asm("mov.b64 %0, {%1, %2};" : "=l"(d) : "f"(lo), "f"(hi));
    return d;
}
__device__ __forceinline__ void unpack2(unsigned long long v, float& lo, float& hi) {
    asm("mov.b64 {%0, %1}, %2;" : "=f"(lo), "=f"(hi) : "l"(v));
}

#define VPT 4   // float4 tiles per thread (16 elements)

__global__ void __launch_bounds__(256) rational_kernel(
    const float4* __restrict__ x,
    float4* __restrict__ out,
    int n4)
{
    // Broadcast coefficient loads (already duplicated {c,c} in g_pq).
    const unsigned long long* pq = (const unsigned long long*)g_pq;
    unsigned long long P[8], Q[8];
#pragma unroll
    for (int i = 0; i < 8; i++) {
        P[i] = __ldg(&pq[i]);
        Q[i] = __ldg(&pq[8 + i]);
    }

    int base = blockIdx.x * (blockDim.x * VPT) + threadIdx.x;

    // Batch loads up front for MLP.
    float4 v[VPT];
    bool ok[VPT];
#pragma unroll
    for (int j = 0; j < VPT; j++) {
        int idx = base + j * 256;
        ok[j] = (idx < n4);
        v[j] = ok[j] ? x[idx] : make_float4(0.f, 0.f, 0.f, 0.f);
    }

#pragma unroll
    for (int j = 0; j < VPT; j++) {
        float T0 = tanh_approx(5.0f * v[j].x);
        float T1 = tanh_approx(5.0f * v[j].y);
        float T2 = tanh_approx(5.0f * v[j].z);
        float T3 = tanh_approx(5.0f * v[j].w);

        unsigned long long Ta = pack2(T0, T1);
        unsigned long long Tb = pack2(T2, T3);

        unsigned long long Pa = P[7], Pb = P[7];
        unsigned long long Qa = Q[7], Qb = Q[7];
#pragma unroll
        for (int i = 6; i >= 0; i--) {
            Pa = fma2(Pa, Ta, P[i]);
            Pb = fma2(Pb, Tb, P[i]);
            Qa = fma2(Qa, Ta, Q[i]);
            Qb = fma2(Qb, Tb, Q[i]);
        }

        float p0, p1, p2, p3, q0, q1, q2, q3;
        unpack2(Pa, p0, p1); unpack2(Pb, p2, p3);
        unpack2(Qa, q0, q1); unpack2(Qb, q2, q3);

        float4 o;
        o.x = p0 * rcp_approx(q0);
        o.y = p1 * rcp_approx(q1);
        o.z = p2 * rcp_approx(q2);
        o.w = p3 * rcp_approx(q3);

        int idx = base + j * 256;
        if (ok[j]) out[idx] = o;
    }
}

extern "C" void kernel_launch(void* const* d_in, const int* in_sizes, int n_in,
                              void* d_out, int out_size)
{
    const float4* x = (const float4*)d_in[0];
    const float*  w = (const float*)d_in[1];
    float4* out = (float4*)d_out;

    int n  = in_sizes[0];        // 8388608
    int n4 = n / 4;              // 2097152

    precompute_kernel<<<1, 32>>>(w);

    const int threads = 256;
    int blocks = (n4 + threads * VPT - 1) / (threads * VPT);   // 2048
    rational_kernel<<<blocks, threads>>>(x, out, n4);
}